// round 15
// baseline (speedup 1.0000x reference)
#include <cuda_runtime.h>

// B=64, T=512, E=8192
// out[b][j] = (1/count) * sum_{r=r0}^{511} x[b*T*E + (j+512) + r*8191]
//   r0 = max(0, j - 7679), count = 512 - r0, j in [0, 8190].
//
// Single kernel, intra-CTA r-split: 1024-thread CTA = 128 j-columns x 8
// r-slices of 64 rows. Each thread sums its slice (two 32-row streams);
// slices 1..7 stash partials in smem; slice 0 combines and writes the mean.
// 4096 CTAs @ 2/SM -> 13.8 waves: half the drain-tail of the 2048-CTA
// variant, zero scratch traffic, zero epilogue launches.

#define B_DIM 64
#define T_DIM 512
#define E_DIM 8192
#define OUT_COLS (E_DIM - 1)          // 8191
#define ROW_STRIDE (E_DIM - 1)        // 8191
#define J_FULL (E_DIM - T_DIM - 1)    // 7679
#define JCOLS 128                     // j per CTA
#define NQ 8                          // r-slices per CTA
#define BLOCK (JCOLS * NQ)            // 1024 threads
#define JTILES (E_DIM / JCOLS)        // 64
#define FULL_TILES 60                 // tiles 0..59: j <= 7679 (full count)
#define R_Q (T_DIM / NQ)              // 64 rows per slice
#define R_H (R_Q / 2)                 // 32 rows per stream
#define H_OFF ((unsigned)(R_H * ROW_STRIDE))

__global__ __launch_bounds__(BLOCK, 2) void antidiag_mean_kernel(
    const float* __restrict__ x, float* __restrict__ out)
{
    __shared__ float s_part[(NQ - 1) * JCOLS];   // 3.5 KB

    const int tid  = threadIdx.x;
    const int jcol = tid & (JCOLS - 1);
    const int q    = tid >> 7;                   // 0..7
    const int jt   = blockIdx.x;
    const int b    = blockIdx.y;
    const int j    = jt * JCOLS + jcol;
    const bool valid = (j < OUT_COLS);

    float s = 0.0f;
    if (valid) {
        const float* __restrict__ p =
            x + (size_t)b * T_DIM * E_DIM + (size_t)(j + T_DIM);
        const int rbeg = q * R_Q;
        if (jt < FULL_TILES) {
            // hot path: full slice, two 32-row streams, unroll 8
            // -> 16 independent LDGs per scoreboard window (proven shape).
            const float* ph = p + (size_t)rbeg * ROW_STRIDE;
            float s0 = 0.f, s1 = 0.f;
            #pragma unroll 8
            for (int r = 0; r < R_H; ++r) {
                const unsigned off = (unsigned)(r * ROW_STRIDE);
                s0 += ph[off];
                s1 += ph[off + H_OFF];
            }
            s = s0 + s1;
        } else {
            // ragged tail (j in [7680, 8190]): clamp slice start to r0
            const int r0 = j - J_FULL;           // >= 1 here
            const int rs = (r0 > rbeg) ? r0 : rbeg;
            const int re = rbeg + R_Q;
            #pragma unroll 8
            for (int r = rs; r < re; ++r)
                s += p[(unsigned)(r * ROW_STRIDE)];
        }
    }

    // slices 1..7 publish partials; slice 0 combines and writes.
    if (q > 0)
        s_part[(q - 1) * JCOLS + jcol] = s;
    __syncthreads();

    if (q == 0 && valid) {
        // consecutive jcol -> consecutive banks: conflict-free LDS.
        float acc = s;
        #pragma unroll
        for (int qq = 0; qq < NQ - 1; ++qq)
            acc += s_part[qq * JCOLS + jcol];
        const int r0 = (j > J_FULL) ? (j - J_FULL) : 0;
        out[(size_t)b * OUT_COLS + j] = acc * (1.0f / (float)(T_DIM - r0));
    }
}

extern "C" void kernel_launch(void* const* d_in, const int* in_sizes, int n_in,
                              void* d_out, int out_size)
{
    const float* x = (const float*)d_in[0];
    float* out = (float*)d_out;

    dim3 block(BLOCK);
    dim3 grid(JTILES, B_DIM);        // 64 x 64 = 4096 CTAs of 1024 threads
    antidiag_mean_kernel<<<grid, block>>>(x, out);
}